// round 11
// baseline (speedup 1.0000x reference)
#include <cuda_runtime.h>
#include <cuda_fp16.h>

#define NU 80000
#define NI 30000
#define NT 110000   // NU + NI
#define DD 64
#define NNZ_ADJ 2000000
#define NNZ_MM  300000

#define ADJ_CAP 64
#define MM_CAP  48

// out layout (float offsets)
#define OFF_UG   0
#define OFF_IG   (NU*DD)
#define OFF_IMG  (OFF_IG + NI*DD)
#define OFF_TXT  (OFF_IMG + NI*DD)
#define OFF_H    (OFF_TXT + NI*DD)

// ---------------- scratch ----------------
__device__ __half g_ego_h[NT*DD];    // fp16 [user_emb ; item_emb]
__device__ __half g_cur1_h[NT*DD];   // fp16 layer-1 adj output
__device__ float  g_ih[2*NI*DD];     // [ipre ; hnorm] contiguous for item tcq

__device__ int  g_cnt[NT + 2*NI];
__device__ int2 g_adj_pairs[(size_t)NT * ADJ_CAP];
__device__ int2 g_img_pairs[(size_t)NI * MM_CAP];
__device__ int2 g_txt_pairs[(size_t)NI * MM_CAP];

// ---------------- bucket build ----------------
__device__ __forceinline__ void bucket4(int4 r, int4 c, float4 v,
                                        int* __restrict__ counts, int2* __restrict__ pairs,
                                        int cap) {
    int p0 = atomicAdd(&counts[r.x], 1);
    int p1 = atomicAdd(&counts[r.y], 1);
    int p2 = atomicAdd(&counts[r.z], 1);
    int p3 = atomicAdd(&counts[r.w], 1);
    if (p0 < cap) pairs[(size_t)r.x * cap + p0] = make_int2(c.x, __float_as_int(v.x));
    if (p1 < cap) pairs[(size_t)r.y * cap + p1] = make_int2(c.y, __float_as_int(v.y));
    if (p2 < cap) pairs[(size_t)r.z * cap + p2] = make_int2(c.z, __float_as_int(v.z));
    if (p3 < cap) pairs[(size_t)r.w * cap + p3] = make_int2(c.w, __float_as_int(v.w));
}

#define TA (NNZ_ADJ/4)
#define TM (NNZ_MM/4)
#define CVT_B ((NT*(DD/4) + 255)/256)
#define BKT_B ((TA + 2*TM + 255)/256)

// ---------------- K1: fp16 ego conversion + bucket builds (fused) ----------------
__global__ __launch_bounds__(256) void k1_prep_kernel(
        const float4* __restrict__ ue, const float4* __restrict__ ie,
        const int4* __restrict__ ar, const int4* __restrict__ ac, const float4* __restrict__ av,
        const int4* __restrict__ ir, const int4* __restrict__ ic, const float4* __restrict__ iv,
        const int4* __restrict__ tr, const int4* __restrict__ tc, const float4* __restrict__ tv) {
    if (blockIdx.x < CVT_B) {
        int i = blockIdx.x * blockDim.x + threadIdx.x;
        if (i >= NT * (DD / 4)) return;
        float4 v = (i < NU * (DD / 4)) ? ue[i] : ie[i - NU * (DD / 4)];
        __half2 h01 = __floats2half2_rn(v.x, v.y);
        __half2 h23 = __floats2half2_rn(v.z, v.w);
        uint2 u;
        u.x = *reinterpret_cast<unsigned*>(&h01);
        u.y = *reinterpret_cast<unsigned*>(&h23);
        reinterpret_cast<uint2*>(g_ego_h)[i] = u;
    } else {
        int t = (blockIdx.x - CVT_B) * blockDim.x + threadIdx.x;
        if (t < TA) {
            bucket4(ar[t], ac[t], av[t], g_cnt, g_adj_pairs, ADJ_CAP);
        } else if (t < TA + TM) {
            int e = t - TA;
            bucket4(ir[e], ic[e], iv[e], g_cnt + NT, g_img_pairs, MM_CAP);
        } else if (t < TA + 2 * TM) {
            int e = t - TA - TM;
            bucket4(tr[e], tc[e], tv[e], g_cnt + NT + NI, g_txt_pairs, MM_CAP);
        }
    }
}

// ---------------- paired-row fp16 gather ----------------
__device__ __forceinline__ float4 gather_row_pair_h(const int2* __restrict__ p_my, int cnt_my,
                                                    int cnt_max, const __half* __restrict__ x,
                                                    int hl) {
    float4 a = make_float4(0.f, 0.f, 0.f, 0.f);
    for (int base = 0; base < cnt_max; base += 16) {
        int j = base + hl;
        int2 pr = (j < cnt_my) ? p_my[j] : make_int2(0, 0);
        int m4 = (min(cnt_max - base, 16) + 3) & ~3;
        for (int k = 0; k < m4; k += 4) {
#pragma unroll
            for (int kk = 0; kk < 4; kk++) {
                int   c = __shfl_sync(0xffffffffu, pr.x, k + kk, 16);
                float v = __int_as_float(__shfl_sync(0xffffffffu, pr.y, k + kk, 16));
                uint2 u = __ldg(reinterpret_cast<const uint2*>(x + (size_t)c * DD) + hl);
                __half2 h01 = *reinterpret_cast<__half2*>(&u.x);
                __half2 h23 = *reinterpret_cast<__half2*>(&u.y);
                float2 f01 = __half22float2(h01);
                float2 f23 = __half22float2(h23);
                a.x = fmaf(v, f01.x, a.x);
                a.y = fmaf(v, f01.y, a.y);
                a.z = fmaf(v, f23.x, a.z);
                a.w = fmaf(v, f23.y, a.w);
            }
        }
    }
    return a;
}

__device__ __forceinline__ void store_half4(__half* __restrict__ dst, int hl, float4 a) {
    __half2 h01 = __floats2half2_rn(a.x, a.y);
    __half2 h23 = __floats2half2_rn(a.z, a.w);
    uint2 u;
    u.x = *reinterpret_cast<unsigned*>(&h01);
    u.y = *reinterpret_cast<unsigned*>(&h23);
    reinterpret_cast<uint2*>(dst)[hl] = u;
}

// ---------------- K2: adj layer 1 + modal gathers ----------------
__global__ __launch_bounds__(256) void k2_gather_kernel(float* __restrict__ out_img,
                                                        float* __restrict__ out_txt) {
    int w = (blockIdx.x * blockDim.x + threadIdx.x) >> 5;
    int lane = threadIdx.x & 31;
    int half = lane >> 4, hl = lane & 15;
    if (w < NT / 2) {
        int row = w * 2 + half;
        int cnt = min(g_cnt[row], ADJ_CAP);
        int cmax = max(cnt, __shfl_xor_sync(0xffffffffu, cnt, 16));
        float4 a = gather_row_pair_h(g_adj_pairs + (size_t)row * ADJ_CAP, cnt, cmax, g_ego_h, hl);
        store_half4(g_cur1_h + (size_t)row * DD, hl, a);
    } else if (w < NT / 2 + NI) {
        int mrow = (w - NT / 2) * 2 + half;
        bool is_img = mrow < NI;
        int row = is_img ? mrow : mrow - NI;
        int cnt = min(is_img ? g_cnt[NT + row] : g_cnt[NT + NI + row], MM_CAP);
        int cmax = max(cnt, __shfl_xor_sync(0xffffffffu, cnt, 16));
        const int2* p = (is_img ? g_img_pairs : g_txt_pairs) + (size_t)row * MM_CAP;
        float4 a = gather_row_pair_h(p, cnt, cmax, g_ego_h + (size_t)NU * DD, hl);
        float* dst = (is_img ? out_img : out_txt) + (size_t)row * DD;
        reinterpret_cast<float4*>(dst)[hl] = a;
    }
}

// ============================================================================
// Fused tcq+combine, 4 items/warp: mma rows 0-3 = X[item] (img/ipre),
// rows 4-7 = X[NI+item] (txt/hnorm), rows 8-15 zero (a1=a3=0, c2/c3 unused).
// 938 blocks => full latency-hiding occupancy. Epilogue does softmax + mix
// (+ norm for MODE 0) and writes results directly.
// ============================================================================
__device__ __forceinline__ unsigned f2h2(float x, float y) {
    __half2 h = __floats2half2_rn(x, y);
    return *reinterpret_cast<unsigned*>(&h);
}

__device__ __forceinline__ float ftanh(float x) {
    x = fminf(fmaxf(x, -15.f), 15.f);
    float e = __expf(2.f * x);
    return (e - 1.f) / (e + 1.f);
}

__device__ __forceinline__ void mma16816(float& c0, float& c1, float& c2, float& c3,
                                         unsigned a0, unsigned a1, unsigned a2, unsigned a3,
                                         unsigned b0, unsigned b1) {
    asm volatile("mma.sync.aligned.m16n8k16.row.col.f32.f16.f16.f32 "
                 "{%0,%1,%2,%3}, {%4,%5,%6,%7}, {%8,%9}, {%0,%1,%2,%3};"
                 : "+f"(c0), "+f"(c1), "+f"(c2), "+f"(c3)
                 : "r"(a0), "r"(a1), "r"(a2), "r"(a3), "r"(b0), "r"(b1));
}

#define WT_STRIDE 72
#define TCQ_ITEMS_PER_BLOCK 32
#define TCQF_BLOCKS ((NI + TCQ_ITEMS_PER_BLOCK - 1) / TCQ_ITEMS_PER_BLOCK)   // 938

// mode 0: modal — write h (h_out) + hnorm (g_ih hi half)
// mode 1: item  — write ig (h_out)
template <int MODE>
__device__ void tcq_combine_body(const float* __restrict__ X,
                                 const float* __restrict__ W, const float* __restrict__ b,
                                 const float* __restrict__ w2,
                                 float* __restrict__ h_out, int bid) {
    __shared__ __half sWt[64 * WT_STRIDE];
    __shared__ float sb[64];
    __shared__ float sw2[64];
    for (int i = threadIdx.x; i < 4096; i += 256) {
        int k = i >> 6, n = i & 63;
        sWt[n * WT_STRIDE + k] = __float2half(W[i]);
    }
    if (threadIdx.x < 64) { sb[threadIdx.x] = b[threadIdx.x]; sw2[threadIdx.x] = w2[threadIdx.x]; }
    __syncthreads();

    int w = threadIdx.x >> 5, lane = threadIdx.x & 31;
    int gr = lane >> 2, tig = lane & 3;
    int base = bid * TCQ_ITEMS_PER_BLOCK + w * 4;
    if (base >= NI) return;
    // row for this thread's A fragment: gr 0-3 -> img/ipre item base+gr,
    //                                   gr 4-7 -> txt/hnorm item base+gr-4
    int r = (gr < 4) ? (base + gr) : (NI + base + gr - 4);

    unsigned ra[4][2];
#pragma unroll
    for (int kt = 0; kt < 4; kt++) {
        const float* x0 = X + (size_t)r * 64 + kt * 16 + tig * 2;
        float2 f0 = *reinterpret_cast<const float2*>(x0);
        float2 f2 = *reinterpret_cast<const float2*>(x0 + 8);
        ra[kt][0] = f2h2(f0.x, f0.y);
        ra[kt][1] = f2h2(f2.x, f2.y);
    }

    float q0 = 0.f;
#pragma unroll
    for (int nt = 0; nt < 8; nt++) {
        float c0 = 0.f, c1 = 0.f, c2 = 0.f, c3 = 0.f;
        int n = nt * 8 + gr;
#pragma unroll
        for (int kt = 0; kt < 4; kt++) {
            int k0 = kt * 16 + tig * 2;
            unsigned b0 = *reinterpret_cast<const unsigned*>(sWt + n * WT_STRIDE + k0);
            unsigned b1 = *reinterpret_cast<const unsigned*>(sWt + n * WT_STRIDE + k0 + 8);
            mma16816(c0, c1, c2, c3, ra[kt][0], 0u, ra[kt][1], 0u, b0, b1);
        }
        int col0 = nt * 8 + tig * 2, col1 = col0 + 1;
        q0 += ftanh(c0 + sb[col0]) * sw2[col0] + ftanh(c1 + sb[col1]) * sw2[col1];
    }
    q0 += __shfl_xor_sync(0xffffffffu, q0, 1);
    q0 += __shfl_xor_sync(0xffffffffu, q0, 2);
    // q for row gr lives at lanes gr*4 (tig==0)

    // epilogue: per-item softmax + mix; lane covers cols [2*lane, 2*lane+2)
#pragma unroll
    for (int t = 0; t < 4; t++) {
        float qa = __shfl_sync(0xffffffffu, q0, t * 4);          // img/ipre query
        float qb = __shfl_sync(0xffffffffu, q0, (t + 4) * 4);    // txt/hnorm query
        float m = fmaxf(qa, qb);
        float e0 = __expf(qa - m), e1 = __expf(qb - m);
        float sinv = 1.f / (e0 + e1);
        float w0 = e0 * sinv, w1 = e1 * sinv;
        int item = base + t;
        float2 av = *reinterpret_cast<const float2*>(X + (size_t)item * 64 + lane * 2);
        float2 bv = *reinterpret_cast<const float2*>(X + (size_t)(NI + item) * 64 + lane * 2);
        float2 h = make_float2(w0 * av.x + w1 * bv.x, w0 * av.y + w1 * bv.y);
        if (MODE == 0) {
            float ss = h.x * h.x + h.y * h.y;
#pragma unroll
            for (int o = 1; o < 32; o <<= 1) ss += __shfl_xor_sync(0xffffffffu, ss, o);
            float rinv = 1.f / fmaxf(sqrtf(ss), 1e-12f);
            *reinterpret_cast<float2*>(h_out + (size_t)item * 64 + lane * 2) = h;
            float2 hn = make_float2(h.x * rinv, h.y * rinv);
            *reinterpret_cast<float2*>(g_ih + (size_t)(NI + item) * 64 + lane * 2) = hn;
        } else {
            *reinterpret_cast<float2*>(h_out + (size_t)item * 64 + lane * 2) = h;
        }
    }
}

// ---------------- adj2 body (paired-row gather + final averaging) ----------------
__device__ void adj2_body(const float4* __restrict__ ue, const float4* __restrict__ ie,
                          float* __restrict__ ug, int bid) {
    int w = (bid * 256 + (int)threadIdx.x) >> 5;
    int lane = threadIdx.x & 31;
    int half = lane >> 4, hl = lane & 15;
    if (w >= NT / 2) return;
    int row = w * 2 + half;
    int cnt = min(g_cnt[row], ADJ_CAP);
    int cmax = max(cnt, __shfl_xor_sync(0xffffffffu, cnt, 16));
    float4 s = gather_row_pair_h(g_adj_pairs + (size_t)row * ADJ_CAP, cnt, cmax, g_cur1_h, hl);
    const float kk = 1.f / 3.f;
    uint2 u = reinterpret_cast<const uint2*>(g_cur1_h + (size_t)row * DD)[hl];
    float2 c01 = __half22float2(*reinterpret_cast<__half2*>(&u.x));
    float2 c23 = __half22float2(*reinterpret_cast<__half2*>(&u.y));
    float4 e = (row < NU) ? ue[row * (DD / 4) + hl]
                          : ie[(row - NU) * (DD / 4) + hl];
    float4 r = make_float4((e.x + c01.x + s.x) * kk, (e.y + c01.y + s.y) * kk,
                           (e.z + c23.x + s.z) * kk, (e.w + c23.y + s.w) * kk);
    if (row < NU) {
        reinterpret_cast<float4*>(ug + (size_t)row * DD)[hl] = r;
    } else {
        reinterpret_cast<float4*>(g_ih + (size_t)(row - NU) * DD)[hl] = r;   // ipre
    }
}

// ---------------- K3: modal tcq+combine (blocks [0,TCQF_BLOCKS)) || adj2 ----------------
__global__ __launch_bounds__(256) void k3_fused_kernel(const float* __restrict__ Xmod,
                                                       const float* __restrict__ Wq1,
                                                       const float* __restrict__ bq1,
                                                       const float* __restrict__ wq2,
                                                       float* __restrict__ h_out,
                                                       const float4* __restrict__ ue,
                                                       const float4* __restrict__ ie,
                                                       float* __restrict__ ug) {
    if (blockIdx.x < TCQF_BLOCKS) {
        tcq_combine_body<0>(Xmod, Wq1, bq1, wq2, h_out, blockIdx.x);
    } else {
        adj2_body(ue, ie, ug, blockIdx.x - TCQF_BLOCKS);
    }
}

// ---------------- K4: item tcq+combine -> ig ----------------
__global__ __launch_bounds__(256) void k4_item_kernel(const float* __restrict__ Wc1,
                                                      const float* __restrict__ bc1,
                                                      const float* __restrict__ wc2,
                                                      float* __restrict__ ig) {
    tcq_combine_body<1>(g_ih, Wc1, bc1, wc2, ig, blockIdx.x);
}

extern "C" void kernel_launch(void* const* d_in, const int* in_sizes, int n_in,
                              void* d_out, int out_size) {
    const float* user_emb = (const float*)d_in[0];
    const float* item_emb = (const float*)d_in[1];
    const float* Wq1 = (const float*)d_in[2];
    const float* bq1 = (const float*)d_in[3];
    const float* wq2 = (const float*)d_in[4];
    const float* Wc1 = (const float*)d_in[5];
    const float* bc1 = (const float*)d_in[6];
    const float* wc2 = (const float*)d_in[7];
    const float* adj_vals = (const float*)d_in[8];
    const float* img_vals = (const float*)d_in[9];
    const float* txt_vals = (const float*)d_in[10];
    const int* adj_rows = (const int*)d_in[11];
    const int* adj_cols = (const int*)d_in[12];
    const int* img_rows = (const int*)d_in[13];
    const int* img_cols = (const int*)d_in[14];
    const int* txt_rows = (const int*)d_in[15];
    const int* txt_cols = (const int*)d_in[16];

    float* out = (float*)d_out;
    float* out_ug  = out + OFF_UG;
    float* out_ig  = out + OFF_IG;
    float* out_img = out + OFF_IMG;
    float* out_txt = out + OFF_TXT;
    float* out_h   = out + OFF_H;

    const int T = 256;

    int* cnt; cudaGetSymbolAddress((void**)&cnt, g_cnt);

    // 0. zero counters
    cudaMemsetAsync(cnt, 0, (NT + 2 * NI) * sizeof(int));

    // 1. fp16 ego conversion + bucket builds (fused)
    k1_prep_kernel<<<CVT_B + BKT_B, T>>>(
        (const float4*)user_emb, (const float4*)item_emb,
        (const int4*)adj_rows, (const int4*)adj_cols, (const float4*)adj_vals,
        (const int4*)img_rows, (const int4*)img_cols, (const float4*)img_vals,
        (const int4*)txt_rows, (const int4*)txt_cols, (const float4*)txt_vals);

    // 2. adj layer 1 + modal gathers
    {
        int nwarps = NT / 2 + NI;
        k2_gather_kernel<<<(nwarps + 7) / 8, T>>>(out_img, out_txt);
    }

    // 3. modal tcq+combine (h, hnorm) || adj layer 2 + final averaging (ug, ipre)
    {
        int adj_blocks = (NT / 2 + 7) / 8;   // 6875
        k3_fused_kernel<<<TCQF_BLOCKS + adj_blocks, T>>>(out_img, Wq1, bq1, wq2, out_h,
                                                         (const float4*)user_emb,
                                                         (const float4*)item_emb, out_ug);
    }

    // 4. item tcq+combine -> ig
    k4_item_kernel<<<TCQF_BLOCKS, T>>>(Wc1, bc1, wc2, out_ig);

    (void)in_sizes; (void)n_in; (void)out_size;
}

// round 12
// speedup vs baseline: 1.2799x; 1.2799x over previous
#include <cuda_runtime.h>
#include <cuda_fp16.h>

#define NU 80000
#define NI 30000
#define NT 110000   // NU + NI
#define DD 64
#define NNZ_ADJ 2000000
#define NNZ_MM  300000

#define ADJ_CAP 64
#define MM_CAP  48

// out layout (float offsets)
#define OFF_UG   0
#define OFF_IG   (NU*DD)
#define OFF_IMG  (OFF_IG + NI*DD)
#define OFF_TXT  (OFF_IMG + NI*DD)
#define OFF_H    (OFF_TXT + NI*DD)

// ---------------- scratch ----------------
__device__ __half g_ego_h[NT*DD];    // fp16 [user_emb ; item_emb]
__device__ __half g_cur1_h[NT*DD];   // fp16 layer-1 adj output
__device__ __half g_ih_h[2*NI*DD];   // fp16 [ipre ; hnorm] for item tcq
__device__ float  g_q[2*NI];         // query outputs

__device__ int  g_cnt[NT + 2*NI];
__device__ int2 g_adj_pairs[(size_t)NT * ADJ_CAP];
__device__ int2 g_img_pairs[(size_t)NI * MM_CAP];
__device__ int2 g_txt_pairs[(size_t)NI * MM_CAP];

// ---------------- bucket build ----------------
__device__ __forceinline__ void bucket4(int4 r, int4 c, float4 v,
                                        int* __restrict__ counts, int2* __restrict__ pairs,
                                        int cap) {
    int p0 = atomicAdd(&counts[r.x], 1);
    int p1 = atomicAdd(&counts[r.y], 1);
    int p2 = atomicAdd(&counts[r.z], 1);
    int p3 = atomicAdd(&counts[r.w], 1);
    if (p0 < cap) pairs[(size_t)r.x * cap + p0] = make_int2(c.x, __float_as_int(v.x));
    if (p1 < cap) pairs[(size_t)r.y * cap + p1] = make_int2(c.y, __float_as_int(v.y));
    if (p2 < cap) pairs[(size_t)r.z * cap + p2] = make_int2(c.z, __float_as_int(v.z));
    if (p3 < cap) pairs[(size_t)r.w * cap + p3] = make_int2(c.w, __float_as_int(v.w));
}

#define TA (NNZ_ADJ/4)
#define TM (NNZ_MM/4)
#define CVT_B ((NT*(DD/4) + 255)/256)
#define BKT_B ((TA + 2*TM + 255)/256)

// ---------------- K1: fp16 ego conversion + bucket builds (fused) ----------------
__global__ __launch_bounds__(256) void k1_prep_kernel(
        const float4* __restrict__ ue, const float4* __restrict__ ie,
        const int4* __restrict__ ar, const int4* __restrict__ ac, const float4* __restrict__ av,
        const int4* __restrict__ ir, const int4* __restrict__ ic, const float4* __restrict__ iv,
        const int4* __restrict__ tr, const int4* __restrict__ tc, const float4* __restrict__ tv) {
    if (blockIdx.x < CVT_B) {
        int i = blockIdx.x * blockDim.x + threadIdx.x;
        if (i >= NT * (DD / 4)) return;
        float4 v = (i < NU * (DD / 4)) ? ue[i] : ie[i - NU * (DD / 4)];
        __half2 h01 = __floats2half2_rn(v.x, v.y);
        __half2 h23 = __floats2half2_rn(v.z, v.w);
        uint2 u;
        u.x = *reinterpret_cast<unsigned*>(&h01);
        u.y = *reinterpret_cast<unsigned*>(&h23);
        reinterpret_cast<uint2*>(g_ego_h)[i] = u;
    } else {
        int t = (blockIdx.x - CVT_B) * blockDim.x + threadIdx.x;
        if (t < TA) {
            bucket4(ar[t], ac[t], av[t], g_cnt, g_adj_pairs, ADJ_CAP);
        } else if (t < TA + TM) {
            int e = t - TA;
            bucket4(ir[e], ic[e], iv[e], g_cnt + NT, g_img_pairs, MM_CAP);
        } else if (t < TA + 2 * TM) {
            int e = t - TA - TM;
            bucket4(tr[e], tc[e], tv[e], g_cnt + NT + NI, g_txt_pairs, MM_CAP);
        }
    }
}

// ---------------- paired-row fp16 gather ----------------
__device__ __forceinline__ float4 gather_row_pair_h(const int2* __restrict__ p_my, int cnt_my,
                                                    int cnt_max, const __half* __restrict__ x,
                                                    int hl) {
    float4 a = make_float4(0.f, 0.f, 0.f, 0.f);
    for (int base = 0; base < cnt_max; base += 16) {
        int j = base + hl;
        int2 pr = (j < cnt_my) ? p_my[j] : make_int2(0, 0);
        int m4 = (min(cnt_max - base, 16) + 3) & ~3;
        for (int k = 0; k < m4; k += 4) {
#pragma unroll
            for (int kk = 0; kk < 4; kk++) {
                int   c = __shfl_sync(0xffffffffu, pr.x, k + kk, 16);
                float v = __int_as_float(__shfl_sync(0xffffffffu, pr.y, k + kk, 16));
                uint2 u = __ldg(reinterpret_cast<const uint2*>(x + (size_t)c * DD) + hl);
                __half2 h01 = *reinterpret_cast<__half2*>(&u.x);
                __half2 h23 = *reinterpret_cast<__half2*>(&u.y);
                float2 f01 = __half22float2(h01);
                float2 f23 = __half22float2(h23);
                a.x = fmaf(v, f01.x, a.x);
                a.y = fmaf(v, f01.y, a.y);
                a.z = fmaf(v, f23.x, a.z);
                a.w = fmaf(v, f23.y, a.w);
            }
        }
    }
    return a;
}

__device__ __forceinline__ void store_half4(__half* __restrict__ dst, int hl, float4 a) {
    __half2 h01 = __floats2half2_rn(a.x, a.y);
    __half2 h23 = __floats2half2_rn(a.z, a.w);
    uint2 u;
    u.x = *reinterpret_cast<unsigned*>(&h01);
    u.y = *reinterpret_cast<unsigned*>(&h23);
    reinterpret_cast<uint2*>(dst)[hl] = u;
}

// ---------------- K2: adj layer 1 + modal gathers ----------------
__global__ __launch_bounds__(256) void k2_gather_kernel(float* __restrict__ out_img,
                                                        float* __restrict__ out_txt) {
    int w = (blockIdx.x * blockDim.x + threadIdx.x) >> 5;
    int lane = threadIdx.x & 31;
    int half = lane >> 4, hl = lane & 15;
    if (w < NT / 2) {
        int row = w * 2 + half;
        int cnt = min(g_cnt[row], ADJ_CAP);
        int cmax = max(cnt, __shfl_xor_sync(0xffffffffu, cnt, 16));
        float4 a = gather_row_pair_h(g_adj_pairs + (size_t)row * ADJ_CAP, cnt, cmax, g_ego_h, hl);
        store_half4(g_cur1_h + (size_t)row * DD, hl, a);
    } else if (w < NT / 2 + NI) {
        int mrow = (w - NT / 2) * 2 + half;
        bool is_img = mrow < NI;
        int row = is_img ? mrow : mrow - NI;
        int cnt = min(is_img ? g_cnt[NT + row] : g_cnt[NT + NI + row], MM_CAP);
        int cmax = max(cnt, __shfl_xor_sync(0xffffffffu, cnt, 16));
        const int2* p = (is_img ? g_img_pairs : g_txt_pairs) + (size_t)row * MM_CAP;
        float4 a = gather_row_pair_h(p, cnt, cmax, g_ego_h + (size_t)NU * DD, hl);
        float* dst = (is_img ? out_img : out_txt) + (size_t)row * DD;
        reinterpret_cast<float4*>(dst)[hl] = a;
    }
}

// ============================================================================
// Tensor-core query body (R9 config): 8 rows/warp, 64 rows/block, q -> g_q.
// Templated on input dtype: fp32 (modal, from d_out) or fp16 (item, g_ih_h).
// ============================================================================
__device__ __forceinline__ unsigned f2h2(float x, float y) {
    __half2 h = __floats2half2_rn(x, y);
    return *reinterpret_cast<unsigned*>(&h);
}

__device__ __forceinline__ float ftanh(float x) {
    x = fminf(fmaxf(x, -15.f), 15.f);
    float e = __expf(2.f * x);
    return (e - 1.f) / (e + 1.f);
}

__device__ __forceinline__ void mma16816(float& c0, float& c1, float& c2, float& c3,
                                         unsigned a0, unsigned a1, unsigned a2, unsigned a3,
                                         unsigned b0, unsigned b1) {
    asm volatile("mma.sync.aligned.m16n8k16.row.col.f32.f16.f16.f32 "
                 "{%0,%1,%2,%3}, {%4,%5,%6,%7}, {%8,%9}, {%0,%1,%2,%3};"
                 : "+f"(c0), "+f"(c1), "+f"(c2), "+f"(c3)
                 : "r"(a0), "r"(a1), "r"(a2), "r"(a3), "r"(b0), "r"(b1));
}

#define WT_STRIDE 72
#define TCQ_ROWS_PER_BLOCK 64
#define TCQ_BLOCKS ((2*NI + TCQ_ROWS_PER_BLOCK - 1) / TCQ_ROWS_PER_BLOCK)   // 938

template <typename XT>
__device__ void tcq_body(const XT* __restrict__ X, int nrows,
                         const float* __restrict__ W, const float* __restrict__ b,
                         const float* __restrict__ w2, float* __restrict__ qout, int bid) {
    __shared__ __half sWt[64 * WT_STRIDE];
    __shared__ float sb[64];
    __shared__ float sw2[64];
    for (int i = threadIdx.x; i < 4096; i += 256) {
        int k = i >> 6, n = i & 63;                    // coalesced read of W
        sWt[n * WT_STRIDE + k] = __float2half(W[i]);
    }
    if (threadIdx.x < 64) { sb[threadIdx.x] = b[threadIdx.x]; sw2[threadIdx.x] = w2[threadIdx.x]; }
    __syncthreads();

    int w = threadIdx.x >> 5, lane = threadIdx.x & 31;
    int gr = lane >> 2, tig = lane & 3;
    int base = bid * TCQ_ROWS_PER_BLOCK + w * 8;
    if (base >= nrows) return;
    int r0 = base + gr;                                // nrows % 8 == 0 => valid

    unsigned ra[4][2];
#pragma unroll
    for (int kt = 0; kt < 4; kt++) {
        if (sizeof(XT) == 4) {
            const float* x0 = reinterpret_cast<const float*>(X) + (size_t)r0 * 64 + kt * 16 + tig * 2;
            float2 f0 = *reinterpret_cast<const float2*>(x0);
            float2 f2 = *reinterpret_cast<const float2*>(x0 + 8);
            ra[kt][0] = f2h2(f0.x, f0.y);
            ra[kt][1] = f2h2(f2.x, f2.y);
        } else {
            const __half* x0 = reinterpret_cast<const __half*>(X) + (size_t)r0 * 64 + kt * 16 + tig * 2;
            ra[kt][0] = *reinterpret_cast<const unsigned*>(x0);       // 4B aligned (tig*2 even)
            ra[kt][1] = *reinterpret_cast<const unsigned*>(x0 + 8);
        }
    }

    float q0 = 0.f;
#pragma unroll
    for (int nt = 0; nt < 8; nt++) {
        float c0 = 0.f, c1 = 0.f, c2 = 0.f, c3 = 0.f;
        int n = nt * 8 + gr;
#pragma unroll
        for (int kt = 0; kt < 4; kt++) {
            int k0 = kt * 16 + tig * 2;
            unsigned b0 = *reinterpret_cast<const unsigned*>(sWt + n * WT_STRIDE + k0);
            unsigned b1 = *reinterpret_cast<const unsigned*>(sWt + n * WT_STRIDE + k0 + 8);
            mma16816(c0, c1, c2, c3, ra[kt][0], 0u, ra[kt][1], 0u, b0, b1);
        }
        int col0 = nt * 8 + tig * 2, col1 = col0 + 1;
        q0 += ftanh(c0 + sb[col0]) * sw2[col0] + ftanh(c1 + sb[col1]) * sw2[col1];
    }
    q0 += __shfl_xor_sync(0xffffffffu, q0, 1);
    q0 += __shfl_xor_sync(0xffffffffu, q0, 2);
    if (tig == 0) qout[r0] = q0;
}

// ---------------- adj2 body (paired-row gather + final averaging) ----------------
__device__ void adj2_body(const float4* __restrict__ ue, const float4* __restrict__ ie,
                          float* __restrict__ ug, int bid) {
    int w = (bid * 256 + (int)threadIdx.x) >> 5;
    int lane = threadIdx.x & 31;
    int half = lane >> 4, hl = lane & 15;
    if (w >= NT / 2) return;
    int row = w * 2 + half;
    int cnt = min(g_cnt[row], ADJ_CAP);
    int cmax = max(cnt, __shfl_xor_sync(0xffffffffu, cnt, 16));
    float4 s = gather_row_pair_h(g_adj_pairs + (size_t)row * ADJ_CAP, cnt, cmax, g_cur1_h, hl);
    const float kk = 1.f / 3.f;
    uint2 u = reinterpret_cast<const uint2*>(g_cur1_h + (size_t)row * DD)[hl];
    float2 c01 = __half22float2(*reinterpret_cast<__half2*>(&u.x));
    float2 c23 = __half22float2(*reinterpret_cast<__half2*>(&u.y));
    float4 e = (row < NU) ? ue[row * (DD / 4) + hl]
                          : ie[(row - NU) * (DD / 4) + hl];
    float4 r = make_float4((e.x + c01.x + s.x) * kk, (e.y + c01.y + s.y) * kk,
                           (e.z + c23.x + s.z) * kk, (e.w + c23.y + s.w) * kk);
    if (row < NU) {
        reinterpret_cast<float4*>(ug + (size_t)row * DD)[hl] = r;
    } else {
        store_half4(g_ih_h + (size_t)(row - NU) * DD, hl, r);   // ipre (fp16)
    }
}

// ---------------- K3: tcq1 (blocks [0,TCQ_BLOCKS)) || adj2 (rest) ----------------
__global__ __launch_bounds__(256) void k3_fused_kernel(const float* __restrict__ Xmod,
                                                       const float* __restrict__ Wq1,
                                                       const float* __restrict__ bq1,
                                                       const float* __restrict__ wq2,
                                                       const float4* __restrict__ ue,
                                                       const float4* __restrict__ ie,
                                                       float* __restrict__ ug) {
    if (blockIdx.x < TCQ_BLOCKS) {
        tcq_body<float>(Xmod, 2 * NI, Wq1, bq1, wq2, g_q, blockIdx.x);
    } else {
        adj2_body(ue, ie, ug, blockIdx.x - TCQ_BLOCKS);
    }
}

// ---------------- K5: tcq2 standalone (fp16 input) ----------------
__global__ __launch_bounds__(256) void tcq2_kernel(const float* __restrict__ Wc1,
                                                   const float* __restrict__ bc1,
                                                   const float* __restrict__ wc2) {
    tcq_body<__half>(g_ih_h, 2 * NI, Wc1, bc1, wc2, g_q, blockIdx.x);
}

// ---------------- K4: combine_mm (hnorm stored fp16) ----------------
__global__ __launch_bounds__(256) void combine_mm_kernel(const float* __restrict__ img,
                                                         const float* __restrict__ txt,
                                                         float* __restrict__ h_out) {
    int w = (blockIdx.x * blockDim.x + threadIdx.x) >> 5;
    int lane = threadIdx.x & 31;
    int half = lane >> 4, hl = lane & 15;
    int item = w * 2 + half;
    if (item >= NI) return;
    float qi = g_q[item], qt = g_q[NI + item];
    float m = fmaxf(qi, qt);
    float e0 = __expf(qi - m), e1 = __expf(qt - m);
    float sinv = 1.f / (e0 + e1);
    float w0 = e0 * sinv, w1 = e1 * sinv;
    float4 iv = reinterpret_cast<const float4*>(img + (size_t)item * DD)[hl];
    float4 tv = reinterpret_cast<const float4*>(txt + (size_t)item * DD)[hl];
    float4 h = make_float4(w0 * iv.x + w1 * tv.x, w0 * iv.y + w1 * tv.y,
                           w0 * iv.z + w1 * tv.z, w0 * iv.w + w1 * tv.w);
    float ss = h.x * h.x + h.y * h.y + h.z * h.z + h.w * h.w;
#pragma unroll
    for (int o = 1; o < 16; o <<= 1) ss += __shfl_xor_sync(0xffffffffu, ss, o, 16);
    float rinv = 1.f / fmaxf(sqrtf(ss), 1e-12f);
    reinterpret_cast<float4*>(h_out + (size_t)item * DD)[hl] = h;
    float4 hn = make_float4(h.x * rinv, h.y * rinv, h.z * rinv, h.w * rinv);
    store_half4(g_ih_h + (size_t)(NI + item) * DD, hl, hn);
}

// ---------------- K6: combine_item (fp16 sources) ----------------
__global__ __launch_bounds__(256) void combine_item_kernel(float* __restrict__ ig) {
    int idx = blockIdx.x * blockDim.x + threadIdx.x;      // one float4 of output per thread
    if (idx >= NI * (DD / 4)) return;
    int item = idx >> 4;
    float q0 = g_q[item], q1 = g_q[NI + item];
    float m = fmaxf(q0, q1);
    float e0 = __expf(q0 - m), e1 = __expf(q1 - m);
    float sinv = 1.f / (e0 + e1);
    float w0 = e0 * sinv, w1 = e1 * sinv;
    uint2 ua = reinterpret_cast<const uint2*>(g_ih_h)[idx];
    uint2 un = reinterpret_cast<const uint2*>(g_ih_h)[NI * (DD / 4) + idx];
    float2 a01 = __half22float2(*reinterpret_cast<__half2*>(&ua.x));
    float2 a23 = __half22float2(*reinterpret_cast<__half2*>(&ua.y));
    float2 n01 = __half22float2(*reinterpret_cast<__half2*>(&un.x));
    float2 n23 = __half22float2(*reinterpret_cast<__half2*>(&un.y));
    float4 r = make_float4(w0 * a01.x + w1 * n01.x, w0 * a01.y + w1 * n01.y,
                           w0 * a23.x + w1 * n23.x, w0 * a23.y + w1 * n23.y);
    reinterpret_cast<float4*>(ig)[idx] = r;
}

extern "C" void kernel_launch(void* const* d_in, const int* in_sizes, int n_in,
                              void* d_out, int out_size) {
    const float* user_emb = (const float*)d_in[0];
    const float* item_emb = (const float*)d_in[1];
    const float* Wq1 = (const float*)d_in[2];
    const float* bq1 = (const float*)d_in[3];
    const float* wq2 = (const float*)d_in[4];
    const float* Wc1 = (const float*)d_in[5];
    const float* bc1 = (const float*)d_in[6];
    const float* wc2 = (const float*)d_in[7];
    const float* adj_vals = (const float*)d_in[8];
    const float* img_vals = (const float*)d_in[9];
    const float* txt_vals = (const float*)d_in[10];
    const int* adj_rows = (const int*)d_in[11];
    const int* adj_cols = (const int*)d_in[12];
    const int* img_rows = (const int*)d_in[13];
    const int* img_cols = (const int*)d_in[14];
    const int* txt_rows = (const int*)d_in[15];
    const int* txt_cols = (const int*)d_in[16];

    float* out = (float*)d_out;
    float* out_ug  = out + OFF_UG;
    float* out_ig  = out + OFF_IG;
    float* out_img = out + OFF_IMG;
    float* out_txt = out + OFF_TXT;
    float* out_h   = out + OFF_H;

    const int T = 256;

    int* cnt; cudaGetSymbolAddress((void**)&cnt, g_cnt);

    // 0. zero counters
    cudaMemsetAsync(cnt, 0, (NT + 2 * NI) * sizeof(int));

    // 1. fp16 ego conversion + bucket builds (fused)
    k1_prep_kernel<<<CVT_B + BKT_B, T>>>(
        (const float4*)user_emb, (const float4*)item_emb,
        (const int4*)adj_rows, (const int4*)adj_cols, (const float4*)adj_vals,
        (const int4*)img_rows, (const int4*)img_cols, (const float4*)img_vals,
        (const int4*)txt_rows, (const int4*)txt_cols, (const float4*)txt_vals);

    // 2. adj layer 1 + modal gathers
    {
        int nwarps = NT / 2 + NI;
        k2_gather_kernel<<<(nwarps + 7) / 8, T>>>(out_img, out_txt);
    }

    // 3. modal queries (tcq blocks first) || adj layer 2 + final averaging
    {
        int adj_blocks = (NT / 2 + 7) / 8;   // 6875
        k3_fused_kernel<<<TCQ_BLOCKS + adj_blocks, T>>>(out_img, Wq1, bq1, wq2,
                                                        (const float4*)user_emb,
                                                        (const float4*)item_emb, out_ug);
    }

    // 4. modal softmax mix -> h (fp32), hnorm (fp16)
    {
        int nwarps = (NI + 1) / 2;
        combine_mm_kernel<<<(nwarps + 7) / 8, T>>>(out_img, out_txt, out_h);
    }

    // 5. item queries over fp16 [ipre ; hnorm]
    tcq2_kernel<<<TCQ_BLOCKS, T>>>(Wc1, bc1, wc2);

    // 6. item cross-attention mix -> ig
    {
        int n = NI * (DD / 4);
        combine_item_kernel<<<(n + T - 1) / T, T>>>(out_ig);
    }

    (void)in_sizes; (void)n_in; (void)out_size;
}